// round 16
// baseline (speedup 1.0000x reference)
#include <cuda_runtime.h>
#include <cuda_fp16.h>
#include <stdint.h>
#include <math.h>

#define Bb 2
#define Tt 2048
#define Dd 512
#define Hh 8

// ---------------- scratch (device globals) ----------------
__device__ __align__(16) __half g_xh  [(size_t)Bb*Tt*Dd];
__device__ __align__(16) __half g_Qh  [(size_t)Hh*Dd*Dd];
__device__ __align__(16) __half g_Ph  [(size_t)Hh*Dd*Dd];
__device__ __align__(16) __half g_W1h [(size_t)2*Dd*Dd];
__device__ __align__(16) __half g_W2h [(size_t)Dd*2*Dd];
__device__ __align__(16) __half g_Wph [(size_t)Dd*Dd];
__device__ __align__(16) __half g_QZh [(size_t)Bb*Hh*Tt*Dd];
__device__ __align__(16) __half g_PZh [(size_t)Bb*Hh*Tt*Dd];
__device__ __align__(16) __half g_Sh  [(size_t)Bb*Hh*Tt*Tt];   // 128 MB
__device__ __align__(16) __half g_Yph [(size_t)Bb*Hh*Tt*Dd];   // 32 MB (f16)
__device__ __align__(16) __half g_Zh  [(size_t)Bb*Tt*Dd];
__device__ __align__(16) __half g_M1h [(size_t)Bb*Tt*2*Dd];
__device__ __align__(16) __half g_Z2h [(size_t)Bb*Tt*Dd];

constexpr int BM = 128, BN = 128, BK = 32, NTHR = 256;

// smem tile geometry (f16)
constexpr int A_PITCH = 80;                  // 32 halves (64B) + 16B pad
constexpr int A_TILE  = BM * A_PITCH;        // 10240
constexpr int BNT_PITCH = 80;
constexpr int BNT_TILE  = BN * BNT_PITCH;    // 10240
constexpr int BNN_PITCH = 272;               // 128 halves (256B) + 16B pad
constexpr int BNN_TILE  = BK * BNN_PITCH;    // 8704

// ---------------- PTX helpers ----------------
__device__ __forceinline__ void ldsm_x4(uint32_t (&r)[4], uint32_t addr) {
    asm volatile("ldmatrix.sync.aligned.m8n8.x4.shared.b16 {%0,%1,%2,%3}, [%4];"
                 : "=r"(r[0]), "=r"(r[1]), "=r"(r[2]), "=r"(r[3]) : "r"(addr));
}
__device__ __forceinline__ void ldsm_x4_t(uint32_t (&r)[4], uint32_t addr) {
    asm volatile("ldmatrix.sync.aligned.m8n8.x4.trans.shared.b16 {%0,%1,%2,%3}, [%4];"
                 : "=r"(r[0]), "=r"(r[1]), "=r"(r[2]), "=r"(r[3]) : "r"(addr));
}
__device__ __forceinline__ void mma16816(float (&d)[4], const uint32_t (&a)[4],
                                         uint32_t b0, uint32_t b1) {
    asm volatile("mma.sync.aligned.m16n8k16.row.col.f32.f16.f16.f32 "
                 "{%0,%1,%2,%3}, {%4,%5,%6,%7}, {%8,%9}, {%0,%1,%2,%3};"
                 : "+f"(d[0]), "+f"(d[1]), "+f"(d[2]), "+f"(d[3])
                 : "r"(a[0]), "r"(a[1]), "r"(a[2]), "r"(a[3]), "r"(b0), "r"(b1));
}
__device__ __forceinline__ uint32_t pack2h(float x0, float x1) {
    __half2 h = __float22half2_rn(make_float2(x0, x1));
    return *reinterpret_cast<uint32_t*>(&h);
}

// ---------------- plain f16 GEMM via mma.sync, 2 CTAs/SM, BK=32 ----------------
// C = alpha * A @ op(B); A, B single f16 planes.
// BNN=false: B is [N,K] (NT). BNN=true: B is [K,N] (NN).
// KLIM: kmax = rowStart + BM. OMODE: 0 = fp32 C, 3 = f16 C.
// DUAL: z >= nzSplit uses Bh2/Ch2 with zeff = z - nzSplit.
// residual (f16) added pre-store when non-null.
// 256 threads, 8 warps, warp tile 64x32; chunk loop unrolled x2 so the
// double-buffer offset is a compile-time constant in each half (ALU cut).
template <bool CAUSAL, bool RELU, bool BNN, bool KLIM, int OMODE, bool DUAL>
__global__ __launch_bounds__(NTHR, 2)
void tc_gemm(const __half* __restrict__ AhAll, const __half* __restrict__ BhAll,
             float* __restrict__ Call, __half* __restrict__ ChAll,
             const __half* __restrict__ Bh2All, __half* __restrict__ Ch2All,
             int nzSplit,
             int K, int lda, int ldb, int ldc,
             int divA, int modA, size_t sA,
             int divB, int modB, size_t sB, size_t sC,
             const float* __restrict__ bias, const __half* __restrict__ residual,
             float alpha)
{
    constexpr int B_TILE = BNN ? BNN_TILE : BNT_TILE;
    constexpr int BUFSZ  = A_TILE + B_TILE;

    extern __shared__ __align__(16) char smem[];
    const int tid = threadIdx.x;
    int z = blockIdx.z;
    const __half* BhSel = BhAll;
    __half* ChSel = ChAll;
    if (DUAL && z >= nzSplit) {
        z -= nzSplit;
        BhSel = Bh2All;
        ChSel = Ch2All;
    }
    const __half* Ah = AhAll + (size_t)((z / divA) % modA) * sA;
    const __half* Bh = BhSel + (size_t)((z / divB) % modB) * sB;

    int by = blockIdx.y;
    if (CAUSAL || KLIM) by = gridDim.y - 1 - by;   // longest tiles first
    const int rowStart = by * BM;
    const int colStart = blockIdx.x * BN;
    if (CAUSAL && colStart > rowStart) return;

    const uint32_t sbase = (uint32_t)__cvta_generic_to_shared(smem);
    const int w = tid >> 5, lane = tid & 31;
    const int wm = (w >> 2) * 64;     // warp M offset (2 groups)
    const int wn = (w & 3) * 32;      // warp N offset (4 groups)

    // warp tile fully above the diagonal -> skip all LDSM/MMA (acc stays 0)
    const bool wskip = CAUSAL && (colStart + wn > rowStart + wm + 63);

    const int kmax = KLIM ? (rowStart + BM) : K;
    const int nchunks = kmax / BK;   // always even (>= 4) for our launches

    float acc[4][4][4];
#pragma unroll
    for (int i = 0; i < 4; i++)
#pragma unroll
        for (int j = 0; j < 4; j++)
#pragma unroll
            for (int q = 0; q < 4; q++) acc[i][j][q] = 0.0f;

    // per-thread staging: 2 units of 16B per operand tile (256 threads)
    const int aRow = tid >> 2;          // 0..63 (+64 for u=1)
    const int aCh  = tid & 3;
    const int bRowNN = tid >> 4;        // 0..15 (+16 for u=1)
    const int bChNN  = tid & 15;

    int offA[2], offB[2];
    const __half* paH[2];
    const __half* pb[2];
#pragma unroll
    for (int u = 0; u < 2; u++) {
        offA[u] = (aRow + u * 64) * A_PITCH + aCh * 16;
        paH[u] = Ah + (size_t)(rowStart + aRow + u * 64) * lda + aCh * 8;
        if (!BNN) {
            offB[u] = (aRow + u * 64) * BNT_PITCH + aCh * 16;
            pb[u] = Bh + (size_t)(colStart + aRow + u * 64) * ldb + aCh * 8;
        } else {
            offB[u] = (bRowNN + u * 16) * BNN_PITCH + bChNN * 16;
            pb[u] = Bh + (size_t)(bRowNN + u * 16) * ldb + colStart + bChNN * 8;
        }
    }
    const int pbStep = BNN ? BK * ldb : BK;

    // ldmatrix base addresses (buffer 0)
    const uint32_t aLd = sbase + (uint32_t)((wm + (lane & 15)) * A_PITCH + (lane >> 4) * 16);
    const uint32_t bLdNT = sbase + A_TILE +
        (uint32_t)((wn + (lane & 15)) * BNT_PITCH + (lane >> 4) * 16);
    const uint32_t bLdNN = sbase + A_TILE +
        (uint32_t)(((lane & 7) + ((lane & 16) >> 1)) * BNN_PITCH +
                   ((wn >> 3) + ((lane >> 3) & 1)) * 16);

    uint4 rA[2], rB[2];

    auto loadTiles = [&]() {
#pragma unroll
        for (int u = 0; u < 2; u++) {
            rA[u] = *reinterpret_cast<const uint4*>(paH[u]);
            rB[u] = *reinterpret_cast<const uint4*>(pb[u]);
            paH[u] += BK; pb[u] += pbStep;
        }
    };
    auto storeTiles = [&](int buf) {
        char* base = smem + buf * BUFSZ;
#pragma unroll
        for (int u = 0; u < 2; u++) {
            *reinterpret_cast<uint4*>(base + offA[u]) = rA[u];
            *reinterpret_cast<uint4*>(base + A_TILE + offB[u]) = rB[u];
        }
    };
    auto mmaChunk = [&](const uint32_t bo) {   // bo is a literal at each call site
#pragma unroll
        for (int ks = 0; ks < 2; ks++) {
            uint32_t aF[4][4], bF[2][4];
#pragma unroll
            for (int mi = 0; mi < 4; mi++)
                ldsm_x4(aF[mi], aLd + bo + (uint32_t)(mi * 16 * A_PITCH + ks * 32));
#pragma unroll
            for (int p = 0; p < 2; p++) {
                if (!BNN)
                    ldsm_x4(bF[p], bLdNT + bo + (uint32_t)(p * 16 * BNT_PITCH + ks * 32));
                else
                    ldsm_x4_t(bF[p], bLdNN + bo + (uint32_t)(p * 32 + ks * 16 * BNN_PITCH));
            }
#pragma unroll
            for (int mi = 0; mi < 4; mi++)
#pragma unroll
                for (int ni = 0; ni < 4; ni++) {
                    const int p = ni >> 1, s = ni & 1;
                    mma16816(acc[mi][ni], aF[mi], bF[p][s], bF[p][s + 2]);
                }
        }
    };

    loadTiles();
    storeTiles(0);
    __syncthreads();

    for (int c = 0; c < nchunks; c += 2) {
        // ---- even chunk: compute buffer 0, stage chunk c+1 into buffer 1 ----
        if (c + 1 < nchunks) loadTiles();
        if (!wskip) mmaChunk(0u);
        if (c + 1 < nchunks) storeTiles(1);
        __syncthreads();
        if (c + 1 >= nchunks) break;
        // ---- odd chunk: compute buffer 1, stage chunk c+2 into buffer 0 ----
        if (c + 2 < nchunks) loadTiles();
        if (!wskip) mmaChunk((uint32_t)BUFSZ);
        if (c + 2 < nchunks) storeTiles(0);
        __syncthreads();
    }

    // ---------------- epilogue ----------------
    float* C = (OMODE == 0) ? Call + (size_t)z * sC : nullptr;
    __half* Ch = (OMODE == 3) ? ChSel + (size_t)z * sC : nullptr;

    const int r0 = rowStart + wm + (lane >> 2);
    const int c0 = colStart + wn + (lane & 3) * 2;
#pragma unroll
    for (int mi = 0; mi < 4; mi++) {
        const int r = r0 + mi * 16;
#pragma unroll
        for (int ni = 0; ni < 4; ni++) {
            const int c = c0 + ni * 8;
            float v00 = acc[mi][ni][0] * alpha, v01 = acc[mi][ni][1] * alpha;
            float v10 = acc[mi][ni][2] * alpha, v11 = acc[mi][ni][3] * alpha;
            if (CAUSAL) {
                if (c > r)         v00 = 0.0f;
                if (c + 1 > r)     v01 = 0.0f;
                if (c > r + 8)     v10 = 0.0f;
                if (c + 1 > r + 8) v11 = 0.0f;
            }
            if (bias) {
                const float bv0 = bias[c], bv1 = bias[c + 1];
                v00 += bv0; v01 += bv1; v10 += bv0; v11 += bv1;
            }
            if (RELU) {
                v00 = fmaxf(v00, 0.0f); v01 = fmaxf(v01, 0.0f);
                v10 = fmaxf(v10, 0.0f); v11 = fmaxf(v11, 0.0f);
            }
            if (residual) {
                const uint32_t q0 = *reinterpret_cast<const uint32_t*>(residual + (size_t)r * ldc + c);
                const uint32_t q1 = *reinterpret_cast<const uint32_t*>(residual + (size_t)(r + 8) * ldc + c);
                const float2 f0 = __half22float2(*reinterpret_cast<const __half2*>(&q0));
                const float2 f1 = __half22float2(*reinterpret_cast<const __half2*>(&q1));
                v00 += f0.x; v01 += f0.y; v10 += f1.x; v11 += f1.y;
            }
            if (OMODE == 0) {
                *reinterpret_cast<float2*>(C + (size_t)r * ldc + c)       = make_float2(v00, v01);
                *reinterpret_cast<float2*>(C + (size_t)(r + 8) * ldc + c) = make_float2(v10, v11);
            } else {
                *reinterpret_cast<uint32_t*>(Ch + (size_t)r * ldc + c)       = pack2h(v00, v01);
                *reinterpret_cast<uint32_t*>(Ch + (size_t)(r + 8) * ldc + c) = pack2h(v10, v11);
            }
        }
    }
}

// ---------------- fused converter: all 6 arrays in one launch ----------------
constexpr int N4_X  = Bb*Tt*Dd/4;
constexpr int N4_Q  = Hh*Dd*Dd/4;
constexpr int N4_P  = Hh*Dd*Dd/4;
constexpr int N4_W1 = 2*Dd*Dd/4;
constexpr int N4_W2 = 2*Dd*Dd/4;
constexpr int N4_WP = Dd*Dd/4;
constexpr int N4_TOTAL = N4_X + N4_Q + N4_P + N4_W1 + N4_W2 + N4_WP;

__global__ __launch_bounds__(256)
void tohalf_all(const float* __restrict__ x, const float* __restrict__ Q,
                const float* __restrict__ P, const float* __restrict__ W1,
                const float* __restrict__ W2, const float* __restrict__ Wp)
{
    int i = blockIdx.x * 256 + threadIdx.x;
    const float* src;
    __half* dst;
    if (i < N4_X)                       { src = x;  dst = g_xh; }
    else if ((i -= N4_X)  < N4_Q)       { src = Q;  dst = g_Qh; }
    else if ((i -= N4_Q)  < N4_P)       { src = P;  dst = g_Ph; }
    else if ((i -= N4_P)  < N4_W1)      { src = W1; dst = g_W1h; }
    else if ((i -= N4_W1) < N4_W2)      { src = W2; dst = g_W2h; }
    else if ((i -= N4_W2) < N4_WP)      { src = Wp; dst = g_Wph; }
    else return;
    const float4 v = reinterpret_cast<const float4*>(src)[i];
    reinterpret_cast<uint2*>(dst)[i] = make_uint2(pack2h(v.x, v.y), pack2h(v.z, v.w));
}

// ---------------- fused head-mean + residual + LayerNorm -> f16 only ----------------
__global__ __launch_bounds__(128)
void ln_reduce(const __half* __restrict__ Yph, const float* __restrict__ X,
               const float* __restrict__ gamma, const float* __restrict__ beta,
               __half* __restrict__ Zh)
{
    const int row = blockIdx.x;          // b*T + t
    const int b = row >> 11, t = row & (Tt - 1);
    const int tid = threadIdx.x;
    const int c0 = tid * 4;

    float a0 = 0.f, a1 = 0.f, a2 = 0.f, a3 = 0.f;
#pragma unroll
    for (int h = 0; h < Hh; h++) {
        const uint2 y2 = *reinterpret_cast<const uint2*>(
            Yph + ((size_t)(b * Hh + h) * Tt + t) * Dd + c0);
        const float2 f0 = __half22float2(*reinterpret_cast<const __half2*>(&y2.x));
        const float2 f1 = __half22float2(*reinterpret_cast<const __half2*>(&y2.y));
        a0 += f0.x; a1 += f0.y; a2 += f1.x; a3 += f1.y;
    }
    const float4 x4 = *reinterpret_cast<const float4*>(X + (size_t)row * Dd + c0);
    float v[4] = { a0 * 0.125f + x4.x, a1 * 0.125f + x4.y,
                   a2 * 0.125f + x4.z, a3 * 0.125f + x4.w };

    float s  = v[0] + v[1] + v[2] + v[3];
    float sq = v[0]*v[0] + v[1]*v[1] + v[2]*v[2] + v[3]*v[3];
#pragma unroll
    for (int o = 16; o > 0; o >>= 1) {
        s  += __shfl_xor_sync(0xffffffffu, s, o);
        sq += __shfl_xor_sync(0xffffffffu, sq, o);
    }
    __shared__ float sh[8];
    __shared__ float s_mean, s_rstd;
    const int wq = tid >> 5, lane = tid & 31;
    if (lane == 0) { sh[wq] = s; sh[4 + wq] = sq; }
    __syncthreads();
    if (tid == 0) {
        float ts = sh[0] + sh[1] + sh[2] + sh[3];
        float tq = sh[4] + sh[5] + sh[6] + sh[7];
        float mean = ts / (float)Dd;
        float var  = tq / (float)Dd - mean * mean;
        s_mean = mean; s_rstd = rsqrtf(var + 1e-5f);
    }
    __syncthreads();
    const float mean = s_mean, rstd = s_rstd;
    float o[4];
#pragma unroll
    for (int i = 0; i < 4; i++) {
        const int c = c0 + i;
        o[i] = (v[i] - mean) * rstd * gamma[c] + beta[c];
    }
    const size_t off = (size_t)row * Dd + c0;
    *reinterpret_cast<uint2*>(Zh + off) = make_uint2(pack2h(o[0], o[1]), pack2h(o[2], o[3]));
}

// ---------------- launcher ----------------
extern "C" void kernel_launch(void* const* d_in, const int* in_sizes, int n_in,
                              void* d_out, int out_size)
{
    (void)in_sizes; (void)n_in; (void)out_size;
    const float* x     = (const float*)d_in[0];
    const float* P     = (const float*)d_in[1];
    const float* Q     = (const float*)d_in[2];
    const float* gamma = (const float*)d_in[3];
    const float* beta  = (const float*)d_in[4];
    const float* W1    = (const float*)d_in[5];
    const float* b1    = (const float*)d_in[6];
    const float* W2    = (const float*)d_in[7];
    const float* b2    = (const float*)d_in[8];
    const float* Wp    = (const float*)d_in[9];
    const float* bp    = (const float*)d_in[10];
    float* out = (float*)d_out;

    __half *xh, *Qh, *Ph, *W1h, *W2h, *Wph;
    __half *QZh, *PZh, *Sh, *Yph, *Zh, *M1h, *Z2h;
    cudaGetSymbolAddress((void**)&xh,  g_xh);
    cudaGetSymbolAddress((void**)&Qh,  g_Qh);
    cudaGetSymbolAddress((void**)&Ph,  g_Ph);
    cudaGetSymbolAddress((void**)&W1h, g_W1h);
    cudaGetSymbolAddress((void**)&W2h, g_W2h);
    cudaGetSymbolAddress((void**)&Wph, g_Wph);
    cudaGetSymbolAddress((void**)&QZh, g_QZh);
    cudaGetSymbolAddress((void**)&PZh, g_PZh);
    cudaGetSymbolAddress((void**)&Sh,  g_Sh);
    cudaGetSymbolAddress((void**)&Yph, g_Yph);
    cudaGetSymbolAddress((void**)&Zh,  g_Zh);
    cudaGetSymbolAddress((void**)&M1h, g_M1h);
    cudaGetSymbolAddress((void**)&Z2h, g_Z2h);

    constexpr int SM_NT = 2 * (A_TILE + BNT_TILE);   // 40960
    constexpr int SM_NN = 2 * (A_TILE + BNN_TILE);   // 37888

    static bool attr_done = false;
    if (!attr_done) {
        // every launched instantiation MUST be listed
        cudaFuncSetAttribute(tc_gemm<false,false,false,false,3,true>,
                             cudaFuncAttributeMaxDynamicSharedMemorySize, SM_NT);
        cudaFuncSetAttribute(tc_gemm<true,false,false,false,3,false>,
                             cudaFuncAttributeMaxDynamicSharedMemorySize, SM_NT);
        cudaFuncSetAttribute(tc_gemm<false,false,true,true,3,false>,
                             cudaFuncAttributeMaxDynamicSharedMemorySize, SM_NN);
        cudaFuncSetAttribute(tc_gemm<false,true,false,false,3,false>,
                             cudaFuncAttributeMaxDynamicSharedMemorySize, SM_NT);
        cudaFuncSetAttribute(tc_gemm<false,false,false,false,3,false>,
                             cudaFuncAttributeMaxDynamicSharedMemorySize, SM_NT);
        cudaFuncSetAttribute(tc_gemm<false,false,false,false,0,false>,
                             cudaFuncAttributeMaxDynamicSharedMemorySize, SM_NT);
        attr_done = true;
    }

    const dim3 blk(NTHR);
    const float inv_sqrt_d = 1.0f / sqrtf((float)Dd);

    // 0) pre-convert inputs / weights to f16 (single launch)
    tohalf_all<<<(N4_TOTAL + 255) / 256, 256>>>(x, Q, P, W1, W2, Wp);

    // 1+2) QZ[z] = x[b] @ Q[h]^T, PZ via DUAL (z >= 16)
    tc_gemm<false,false,false,false,3,true><<<dim3(4, 16, 32), blk, SM_NT>>>(
        xh, Qh, nullptr, QZh, Ph, PZh, 16,
        Dd, Dd, Dd, Dd,
        Hh, Bb, (size_t)Tt * Dd,
        1,  Hh, (size_t)Dd * Dd,
        (size_t)Tt * Dd, nullptr, nullptr, 1.0f);

    // 3) S[z] = tril(QZ[z] @ x[b]^T) / sqrt(D) -> f16
    tc_gemm<true,false,false,false,3,false><<<dim3(16, 16, 16), blk, SM_NT>>>(
        QZh, xh, nullptr, Sh, nullptr, nullptr, 0,
        Dd, Dd, Dd, Tt,
        1, Bb * Hh, (size_t)Tt * Dd,
        Hh, Bb,     (size_t)Tt * Dd,
        (size_t)Tt * Tt, nullptr, nullptr, inv_sqrt_d);

    // 4) Yp[z] = S[z] @ PZ[z]  (NN, causal K-limit) -> f16
    tc_gemm<false,false,true,true,3,false><<<dim3(4, 16, 16), blk, SM_NN>>>(
        Sh, PZh, nullptr, Yph, nullptr, nullptr, 0,
        Tt, Tt, Dd, Dd,
        1, Bb * Hh, (size_t)Tt * Tt,
        1, Bb * Hh, (size_t)Tt * Dd,
        (size_t)Tt * Dd, nullptr, nullptr, 1.0f);

    // 5) Zh = LayerNorm(mean_h(Yp) + x)  (f16)
    ln_reduce<<<Bb * Tt, 128>>>(Yph, x, gamma, beta, Zh);

    // 6) M1 = relu(Zh @ W1^T + b1) -> f16
    tc_gemm<false,true,false,false,3,false><<<dim3(8, 32, 1), blk, SM_NT>>>(
        Zh, W1h, nullptr, M1h, nullptr, nullptr, 0,
        Dd, Dd, Dd, 2 * Dd,
        1, 1, 0, 1, 1, 0, 0, b1, nullptr, 1.0f);

    // 7) Z2 = Zh + (M1 @ W2^T + b2) -> f16
    tc_gemm<false,false,false,false,3,false><<<dim3(4, 32, 1), blk, SM_NT>>>(
        M1h, W2h, nullptr, Z2h, nullptr, nullptr, 0,
        2 * Dd, 2 * Dd, 2 * Dd, Dd,
        1, 1, 0, 1, 1, 0, 0, b2, Zh, 1.0f);

    // 8) out = Z2 @ Wp^T + bp -> fp32
    tc_gemm<false,false,false,false,0,false><<<dim3(4, 32, 1), blk, SM_NT>>>(
        Z2h, Wph, out, nullptr, nullptr, nullptr, 0,
        Dd, Dd, Dd, Dd,
        1, 1, 0, 1, 1, 0, 0, bp, nullptr, 1.0f);
}

// round 17
// speedup vs baseline: 1.0119x; 1.0119x over previous
#include <cuda_runtime.h>
#include <cuda_fp16.h>
#include <stdint.h>
#include <math.h>

#define Bb 2
#define Tt 2048
#define Dd 512
#define Hh 8

// ---------------- scratch (device globals) ----------------
__device__ __align__(16) __half g_xh  [(size_t)Bb*Tt*Dd];
__device__ __align__(16) __half g_Qh  [(size_t)Hh*Dd*Dd];
__device__ __align__(16) __half g_Ph  [(size_t)Hh*Dd*Dd];
__device__ __align__(16) __half g_W1h [(size_t)2*Dd*Dd];
__device__ __align__(16) __half g_W2h [(size_t)Dd*2*Dd];
__device__ __align__(16) __half g_Wph [(size_t)Dd*Dd];
__device__ __align__(16) __half g_QZh [(size_t)Bb*Hh*Tt*Dd];
__device__ __align__(16) __half g_PZh [(size_t)Bb*Hh*Tt*Dd];
__device__ __align__(16) __half g_Sh  [(size_t)Bb*Hh*Tt*Tt];   // 128 MB
__device__ __align__(16) __half g_Yph [(size_t)Bb*Hh*Tt*Dd];   // 32 MB (f16)
__device__ __align__(16) __half g_Zh  [(size_t)Bb*Tt*Dd];
__device__ __align__(16) __half g_M1h [(size_t)Bb*Tt*2*Dd];
__device__ __align__(16) __half g_Z2h [(size_t)Bb*Tt*Dd];

constexpr int BM = 128, BN = 128, BK = 32, NTHR = 256;

// smem tile geometry (f16)
constexpr int A_PITCH = 80;                  // 32 halves (64B) + 16B pad
constexpr int A_TILE  = BM * A_PITCH;        // 10240
constexpr int BNT_PITCH = 80;
constexpr int BNT_TILE  = BN * BNT_PITCH;    // 10240
constexpr int BNN_PITCH = 272;               // 128 halves (256B) + 16B pad
constexpr int BNN_TILE  = BK * BNN_PITCH;    // 8704

// ---------------- PTX helpers ----------------
__device__ __forceinline__ void ldsm_x4(uint32_t (&r)[4], uint32_t addr) {
    asm volatile("ldmatrix.sync.aligned.m8n8.x4.shared.b16 {%0,%1,%2,%3}, [%4];"
                 : "=r"(r[0]), "=r"(r[1]), "=r"(r[2]), "=r"(r[3]) : "r"(addr));
}
__device__ __forceinline__ void ldsm_x4_t(uint32_t (&r)[4], uint32_t addr) {
    asm volatile("ldmatrix.sync.aligned.m8n8.x4.trans.shared.b16 {%0,%1,%2,%3}, [%4];"
                 : "=r"(r[0]), "=r"(r[1]), "=r"(r[2]), "=r"(r[3]) : "r"(addr));
}
__device__ __forceinline__ void mma16816(float (&d)[4], const uint32_t (&a)[4],
                                         uint32_t b0, uint32_t b1) {
    asm volatile("mma.sync.aligned.m16n8k16.row.col.f32.f16.f16.f32 "
                 "{%0,%1,%2,%3}, {%4,%5,%6,%7}, {%8,%9}, {%0,%1,%2,%3};"
                 : "+f"(d[0]), "+f"(d[1]), "+f"(d[2]), "+f"(d[3])
                 : "r"(a[0]), "r"(a[1]), "r"(a[2]), "r"(a[3]), "r"(b0), "r"(b1));
}
__device__ __forceinline__ uint32_t pack2h(float x0, float x1) {
    __half2 h = __float22half2_rn(make_float2(x0, x1));
    return *reinterpret_cast<uint32_t*>(&h);
}

// ---------------- plain f16 GEMM via mma.sync, 2 CTAs/SM, BK=32 ----------------
// C = alpha * A @ op(B); A, B single f16 planes.
// BNN=false: B is [N,K] (NT). BNN=true: B is [K,N] (NN).
// KLIM: kmax = rowStart + BM. OMODE: 0 = fp32 C, 3 = f16 C.
// DUAL: z >= nzSplit uses Bh2/Ch2 with zeff = z - nzSplit.
// residual (f16) added pre-store when non-null.
// 256 threads, 8 warps, warp tile 64x32; warp-granularity causal skip only.
template <bool CAUSAL, bool RELU, bool BNN, bool KLIM, int OMODE, bool DUAL>
__global__ __launch_bounds__(NTHR, 2)
void tc_gemm(const __half* __restrict__ AhAll, const __half* __restrict__ BhAll,
             float* __restrict__ Call, __half* __restrict__ ChAll,
             const __half* __restrict__ Bh2All, __half* __restrict__ Ch2All,
             int nzSplit,
             int K, int lda, int ldb, int ldc,
             int divA, int modA, size_t sA,
             int divB, int modB, size_t sB, size_t sC,
             const float* __restrict__ bias, const __half* __restrict__ residual,
             float alpha)
{
    constexpr int B_TILE = BNN ? BNN_TILE : BNT_TILE;
    constexpr int BUFSZ  = A_TILE + B_TILE;

    extern __shared__ __align__(16) char smem[];
    const int tid = threadIdx.x;
    int z = blockIdx.z;
    const __half* BhSel = BhAll;
    __half* ChSel = ChAll;
    if (DUAL && z >= nzSplit) {
        z -= nzSplit;
        BhSel = Bh2All;
        ChSel = Ch2All;
    }
    const __half* Ah = AhAll + (size_t)((z / divA) % modA) * sA;
    const __half* Bh = BhSel + (size_t)((z / divB) % modB) * sB;

    int by = blockIdx.y;
    if (CAUSAL || KLIM) by = gridDim.y - 1 - by;   // longest tiles first
    const int rowStart = by * BM;
    const int colStart = blockIdx.x * BN;
    if (CAUSAL && colStart > rowStart) return;

    const uint32_t sbase = (uint32_t)__cvta_generic_to_shared(smem);
    const int w = tid >> 5, lane = tid & 31;
    const int wm = (w >> 2) * 64;     // warp M offset (2 groups)
    const int wn = (w & 3) * 32;      // warp N offset (4 groups)

    // warp tile fully above the diagonal -> skip all LDSM/MMA (acc stays 0)
    const bool wskip = CAUSAL && (colStart + wn > rowStart + wm + 63);

    const int kmax = KLIM ? (rowStart + BM) : K;
    const int nchunks = kmax / BK;

    float acc[4][4][4];
#pragma unroll
    for (int i = 0; i < 4; i++)
#pragma unroll
        for (int j = 0; j < 4; j++)
#pragma unroll
            for (int q = 0; q < 4; q++) acc[i][j][q] = 0.0f;

    // per-thread staging: 2 units of 16B per operand tile (256 threads)
    const int aRow = tid >> 2;          // 0..63 (+64 for u=1)
    const int aCh  = tid & 3;
    const int bRowNN = tid >> 4;        // 0..15 (+16 for u=1)
    const int bChNN  = tid & 15;

    int offA[2], offB[2];
    const __half* paH[2];
    const __half* pb[2];
#pragma unroll
    for (int u = 0; u < 2; u++) {
        offA[u] = (aRow + u * 64) * A_PITCH + aCh * 16;
        paH[u] = Ah + (size_t)(rowStart + aRow + u * 64) * lda + aCh * 8;
        if (!BNN) {
            offB[u] = (aRow + u * 64) * BNT_PITCH + aCh * 16;
            pb[u] = Bh + (size_t)(colStart + aRow + u * 64) * ldb + aCh * 8;
        } else {
            offB[u] = (bRowNN + u * 16) * BNN_PITCH + bChNN * 16;
            pb[u] = Bh + (size_t)(bRowNN + u * 16) * ldb + colStart + bChNN * 8;
        }
    }
    const int pbStep = BNN ? BK * ldb : BK;

    // ldmatrix base addresses (buffer 0)
    const uint32_t aLd = sbase + (uint32_t)((wm + (lane & 15)) * A_PITCH + (lane >> 4) * 16);
    const uint32_t bLdNT = sbase + A_TILE +
        (uint32_t)((wn + (lane & 15)) * BNT_PITCH + (lane >> 4) * 16);
    const uint32_t bLdNN = sbase + A_TILE +
        (uint32_t)(((lane & 7) + ((lane & 16) >> 1)) * BNN_PITCH +
                   ((wn >> 3) + ((lane >> 3) & 1)) * 16);

    uint4 rA[2], rB[2];

    auto loadTiles = [&]() {
#pragma unroll
        for (int u = 0; u < 2; u++) {
            rA[u] = *reinterpret_cast<const uint4*>(paH[u]);
            rB[u] = *reinterpret_cast<const uint4*>(pb[u]);
            paH[u] += BK; pb[u] += pbStep;
        }
    };
    auto storeTiles = [&](int buf) {
        char* base = smem + buf * BUFSZ;
#pragma unroll
        for (int u = 0; u < 2; u++) {
            *reinterpret_cast<uint4*>(base + offA[u]) = rA[u];
            *reinterpret_cast<uint4*>(base + A_TILE + offB[u]) = rB[u];
        }
    };

    loadTiles();
    storeTiles(0);
    __syncthreads();

    for (int c = 0; c < nchunks; c++) {
        const uint32_t bo = (uint32_t)((c & 1) * BUFSZ);
        if (c + 1 < nchunks) loadTiles();

        if (!wskip) {
#pragma unroll
            for (int ks = 0; ks < 2; ks++) {
                uint32_t aF[4][4], bF[2][4];
#pragma unroll
                for (int mi = 0; mi < 4; mi++)
                    ldsm_x4(aF[mi], aLd + bo + (uint32_t)(mi * 16 * A_PITCH + ks * 32));
#pragma unroll
                for (int p = 0; p < 2; p++) {
                    if (!BNN)
                        ldsm_x4(bF[p], bLdNT + bo + (uint32_t)(p * 16 * BNT_PITCH + ks * 32));
                    else
                        ldsm_x4_t(bF[p], bLdNN + bo + (uint32_t)(p * 32 + ks * 16 * BNN_PITCH));
                }
#pragma unroll
                for (int mi = 0; mi < 4; mi++)
#pragma unroll
                    for (int ni = 0; ni < 4; ni++) {
                        const int p = ni >> 1, s = ni & 1;
                        mma16816(acc[mi][ni], aF[mi], bF[p][s], bF[p][s + 2]);
                    }
            }
        }

        if (c + 1 < nchunks) storeTiles((c + 1) & 1);
        __syncthreads();
    }

    // ---------------- epilogue ----------------
    float* C = (OMODE == 0) ? Call + (size_t)z * sC : nullptr;
    __half* Ch = (OMODE == 3) ? ChSel + (size_t)z * sC : nullptr;

    const int r0 = rowStart + wm + (lane >> 2);
    const int c0 = colStart + wn + (lane & 3) * 2;
#pragma unroll
    for (int mi = 0; mi < 4; mi++) {
        const int r = r0 + mi * 16;
#pragma unroll
        for (int ni = 0; ni < 4; ni++) {
            const int c = c0 + ni * 8;
            float v00 = acc[mi][ni][0] * alpha, v01 = acc[mi][ni][1] * alpha;
            float v10 = acc[mi][ni][2] * alpha, v11 = acc[mi][ni][3] * alpha;
            if (CAUSAL) {
                if (c > r)         v00 = 0.0f;
                if (c + 1 > r)     v01 = 0.0f;
                if (c > r + 8)     v10 = 0.0f;
                if (c + 1 > r + 8) v11 = 0.0f;
            }
            if (bias) {
                const float bv0 = bias[c], bv1 = bias[c + 1];
                v00 += bv0; v01 += bv1; v10 += bv0; v11 += bv1;
            }
            if (RELU) {
                v00 = fmaxf(v00, 0.0f); v01 = fmaxf(v01, 0.0f);
                v10 = fmaxf(v10, 0.0f); v11 = fmaxf(v11, 0.0f);
            }
            if (residual) {
                const uint32_t q0 = *reinterpret_cast<const uint32_t*>(residual + (size_t)r * ldc + c);
                const uint32_t q1 = *reinterpret_cast<const uint32_t*>(residual + (size_t)(r + 8) * ldc + c);
                const float2 f0 = __half22float2(*reinterpret_cast<const __half2*>(&q0));
                const float2 f1 = __half22float2(*reinterpret_cast<const __half2*>(&q1));
                v00 += f0.x; v01 += f0.y; v10 += f1.x; v11 += f1.y;
            }
            if (OMODE == 0) {
                *reinterpret_cast<float2*>(C + (size_t)r * ldc + c)       = make_float2(v00, v01);
                *reinterpret_cast<float2*>(C + (size_t)(r + 8) * ldc + c) = make_float2(v10, v11);
            } else {
                *reinterpret_cast<uint32_t*>(Ch + (size_t)r * ldc + c)       = pack2h(v00, v01);
                *reinterpret_cast<uint32_t*>(Ch + (size_t)(r + 8) * ldc + c) = pack2h(v10, v11);
            }
        }
    }
}

// ---------------- fused converter: all 6 arrays in one launch ----------------
constexpr int N4_X  = Bb*Tt*Dd/4;
constexpr int N4_Q  = Hh*Dd*Dd/4;
constexpr int N4_P  = Hh*Dd*Dd/4;
constexpr int N4_W1 = 2*Dd*Dd/4;
constexpr int N4_W2 = 2*Dd*Dd/4;
constexpr int N4_WP = Dd*Dd/4;
constexpr int N4_TOTAL = N4_X + N4_Q + N4_P + N4_W1 + N4_W2 + N4_WP;

__global__ __launch_bounds__(256)
void tohalf_all(const float* __restrict__ x, const float* __restrict__ Q,
                const float* __restrict__ P, const float* __restrict__ W1,
                const float* __restrict__ W2, const float* __restrict__ Wp)
{
    int i = blockIdx.x * 256 + threadIdx.x;
    const float* src;
    __half* dst;
    if (i < N4_X)                       { src = x;  dst = g_xh; }
    else if ((i -= N4_X)  < N4_Q)       { src = Q;  dst = g_Qh; }
    else if ((i -= N4_Q)  < N4_P)       { src = P;  dst = g_Ph; }
    else if ((i -= N4_P)  < N4_W1)      { src = W1; dst = g_W1h; }
    else if ((i -= N4_W1) < N4_W2)      { src = W2; dst = g_W2h; }
    else if ((i -= N4_W2) < N4_WP)      { src = Wp; dst = g_Wph; }
    else return;
    const float4 v = reinterpret_cast<const float4*>(src)[i];
    reinterpret_cast<uint2*>(dst)[i] = make_uint2(pack2h(v.x, v.y), pack2h(v.z, v.w));
}

// ---------------- fused head-mean + residual + LayerNorm -> f16 only ----------------
__global__ __launch_bounds__(128)
void ln_reduce(const __half* __restrict__ Yph, const float* __restrict__ X,
               const float* __restrict__ gamma, const float* __restrict__ beta,
               __half* __restrict__ Zh)
{
    const int row = blockIdx.x;          // b*T + t
    const int b = row >> 11, t = row & (Tt - 1);
    const int tid = threadIdx.x;
    const int c0 = tid * 4;

    float a0 = 0.f, a1 = 0.f, a2 = 0.f, a3 = 0.f;
#pragma unroll
    for (int h = 0; h < Hh; h++) {
        const uint2 y2 = *reinterpret_cast<const uint2*>(
            Yph + ((size_t)(b * Hh + h) * Tt + t) * Dd + c0);
        const float2 f0 = __half22float2(*reinterpret_cast<const __half2*>(&y2.x));
        const float2 f1 = __half22float2(*reinterpret_cast<const __half2*>(&y2.y));
        a0 += f0.x; a1 += f0.y; a2 += f1.x; a3 += f1.y;
    }
    const float4 x4 = *reinterpret_cast<const float4*>(X + (size_t)row * Dd + c0);
    float v[4] = { a0 * 0.125f + x4.x, a1 * 0.125f + x4.y,
                   a2 * 0.125f + x4.z, a3 * 0.125f + x4.w };

    float s  = v[0] + v[1] + v[2] + v[3];
    float sq = v[0]*v[0] + v[1]*v[1] + v[2]*v[2] + v[3]*v[3];
#pragma unroll
    for (int o = 16; o > 0; o >>= 1) {
        s  += __shfl_xor_sync(0xffffffffu, s, o);
        sq += __shfl_xor_sync(0xffffffffu, sq, o);
    }
    __shared__ float sh[8];
    __shared__ float s_mean, s_rstd;
    const int wq = tid >> 5, lane = tid & 31;
    if (lane == 0) { sh[wq] = s; sh[4 + wq] = sq; }
    __syncthreads();
    if (tid == 0) {
        float ts = sh[0] + sh[1] + sh[2] + sh[3];
        float tq = sh[4] + sh[5] + sh[6] + sh[7];
        float mean = ts / (float)Dd;
        float var  = tq / (float)Dd - mean * mean;
        s_mean = mean; s_rstd = rsqrtf(var + 1e-5f);
    }
    __syncthreads();
    const float mean = s_mean, rstd = s_rstd;
    float o[4];
#pragma unroll
    for (int i = 0; i < 4; i++) {
        const int c = c0 + i;
        o[i] = (v[i] - mean) * rstd * gamma[c] + beta[c];
    }
    const size_t off = (size_t)row * Dd + c0;
    *reinterpret_cast<uint2*>(Zh + off) = make_uint2(pack2h(o[0], o[1]), pack2h(o[2], o[3]));
}

// ---------------- launcher ----------------
extern "C" void kernel_launch(void* const* d_in, const int* in_sizes, int n_in,
                              void* d_out, int out_size)
{
    (void)in_sizes; (void)n_in; (void)out_size;
    const float* x     = (const float*)d_in[0];
    const float* P     = (const float*)d_in[1];
    const float* Q     = (const float*)d_in[2];
    const float* gamma = (const float*)d_in[3];
    const float* beta  = (const float*)d_in[4];
    const float* W1    = (const float*)d_in[5];
    const float* b1    = (const float*)d_in[6];
    const float* W2    = (const float*)d_in[7];
    const float* b2    = (const float*)d_in[8];
    const float* Wp    = (const float*)d_in[9];
    const float* bp    = (const float*)d_in[10];
    float* out = (float*)d_out;

    __half *xh, *Qh, *Ph, *W1h, *W2h, *Wph;
    __half *QZh, *PZh, *Sh, *Yph, *Zh, *M1h, *Z2h;
    cudaGetSymbolAddress((void**)&xh,  g_xh);
    cudaGetSymbolAddress((void**)&Qh,  g_Qh);
    cudaGetSymbolAddress((void**)&Ph,  g_Ph);
    cudaGetSymbolAddress((void**)&W1h, g_W1h);
    cudaGetSymbolAddress((void**)&W2h, g_W2h);
    cudaGetSymbolAddress((void**)&Wph, g_Wph);
    cudaGetSymbolAddress((void**)&QZh, g_QZh);
    cudaGetSymbolAddress((void**)&PZh, g_PZh);
    cudaGetSymbolAddress((void**)&Sh,  g_Sh);
    cudaGetSymbolAddress((void**)&Yph, g_Yph);
    cudaGetSymbolAddress((void**)&Zh,  g_Zh);
    cudaGetSymbolAddress((void**)&M1h, g_M1h);
    cudaGetSymbolAddress((void**)&Z2h, g_Z2h);

    constexpr int SM_NT = 2 * (A_TILE + BNT_TILE);   // 40960
    constexpr int SM_NN = 2 * (A_TILE + BNN_TILE);   // 37888

    static bool attr_done = false;
    if (!attr_done) {
        // every launched instantiation MUST be listed
        cudaFuncSetAttribute(tc_gemm<false,false,false,false,3,true>,
                             cudaFuncAttributeMaxDynamicSharedMemorySize, SM_NT);
        cudaFuncSetAttribute(tc_gemm<true,false,false,false,3,false>,
                             cudaFuncAttributeMaxDynamicSharedMemorySize, SM_NT);
        cudaFuncSetAttribute(tc_gemm<false,false,true,true,3,false>,
                             cudaFuncAttributeMaxDynamicSharedMemorySize, SM_NN);
        cudaFuncSetAttribute(tc_gemm<false,true,false,false,3,false>,
                             cudaFuncAttributeMaxDynamicSharedMemorySize, SM_NT);
        cudaFuncSetAttribute(tc_gemm<false,false,false,false,3,false>,
                             cudaFuncAttributeMaxDynamicSharedMemorySize, SM_NT);
        cudaFuncSetAttribute(tc_gemm<false,false,false,false,0,false>,
                             cudaFuncAttributeMaxDynamicSharedMemorySize, SM_NT);
        attr_done = true;
    }

    const dim3 blk(NTHR);
    const float inv_sqrt_d = 1.0f / sqrtf((float)Dd);

    // 0) pre-convert inputs / weights to f16 (single launch)
    tohalf_all<<<(N4_TOTAL + 255) / 256, 256>>>(x, Q, P, W1, W2, Wp);

    // 1+2) QZ[z] = x[b] @ Q[h]^T, PZ via DUAL (z >= 16)
    tc_gemm<false,false,false,false,3,true><<<dim3(4, 16, 32), blk, SM_NT>>>(
        xh, Qh, nullptr, QZh, Ph, PZh, 16,
        Dd, Dd, Dd, Dd,
        Hh, Bb, (size_t)Tt * Dd,
        1,  Hh, (size_t)Dd * Dd,
        (size_t)Tt * Dd, nullptr, nullptr, 1.0f);

    // 3) S[z] = tril(QZ[z] @ x[b]^T) / sqrt(D) -> f16
    tc_gemm<true,false,false,false,3,false><<<dim3(16, 16, 16), blk, SM_NT>>>(
        QZh, xh, nullptr, Sh, nullptr, nullptr, 0,
        Dd, Dd, Dd, Tt,
        1, Bb * Hh, (size_t)Tt * Dd,
        Hh, Bb,     (size_t)Tt * Dd,
        (size_t)Tt * Tt, nullptr, nullptr, inv_sqrt_d);

    // 4) Yp[z] = S[z] @ PZ[z]  (NN, causal K-limit) -> f16
    tc_gemm<false,false,true,true,3,false><<<dim3(4, 16, 16), blk, SM_NN>>>(
        Sh, PZh, nullptr, Yph, nullptr, nullptr, 0,
        Tt, Tt, Dd, Dd,
        1, Bb * Hh, (size_t)Tt * Tt,
        1, Bb * Hh, (size_t)Tt * Dd,
        (size_t)Tt * Dd, nullptr, nullptr, 1.0f);

    // 5) Zh = LayerNorm(mean_h(Yp) + x)  (f16)
    ln_reduce<<<Bb * Tt, 128>>>(Yph, x, gamma, beta, Zh);

    // 6) M1 = relu(Zh @ W1^T + b1) -> f16
    tc_gemm<false,true,false,false,3,false><<<dim3(8, 32, 1), blk, SM_NT>>>(
        Zh, W1h, nullptr, M1h, nullptr, nullptr, 0,
        Dd, Dd, Dd, 2 * Dd,
        1, 1, 0, 1, 1, 0, 0, b1, nullptr, 1.0f);

    // 7) Z2 = Zh + (M1 @ W2^T + b2) -> f16
    tc_gemm<false,false,false,false,3,false><<<dim3(4, 32, 1), blk, SM_NT>>>(
        M1h, W2h, nullptr, Z2h, nullptr, nullptr, 0,
        2 * Dd, 2 * Dd, 2 * Dd, Dd,
        1, 1, 0, 1, 1, 0, 0, b2, Zh, 1.0f);

    // 8) out = Z2 @ Wp^T + bp -> fp32
    tc_gemm<false,false,false,false,0,false><<<dim3(4, 32, 1), blk, SM_NT>>>(
        Z2h, Wph, out, nullptr, nullptr, nullptr, 0,
        Dd, Dd, Dd, Dd,
        1, 1, 0, 1, 1, 0, 0, bp, nullptr, 1.0f);
}